// round 17
// baseline (speedup 1.0000x reference)
#include <cuda_runtime.h>
#include <cuda_fp16.h>
#include <mma.h>
#include <stdint.h>
#include <math.h>

using namespace nvcuda;

#define NT 1024
#define HD 128
#define ED 64
#define SC 32
#define PP 32
#define B1D 512
#define B2D 1024
#define M1D 1024
#define TS 12
#define KM1 (HD + B2D)   // 1152
#define BN_INV_F 0.9999950000374997f

// ---------------- device state / scratch ----------------
static __device__ float g_c[NT * HD];
static __device__ float g_lp[NT * 2];
static __device__ float g_hpre[NT * B1D];
static __device__ float g_gates[NT * 4 * HD];
// folded scalar weights
static __device__ float g_A[B1D], g_B[B1D], g_bias1[B1D];
static __device__ float g_bias2[B2D], g_bm1[M1D], g_bm2[HD];
static __device__ float g_Lb[4 * HD];
// pre-tiled fp16 weights: [nb][chunk64][128r x 64k] tiles (8192 halfs)
static __device__ __half g_W2th[8 * 8 * 8192];
static __device__ __half g_M1th[8 * 18 * 8192];
static __device__ __half g_M2th[16 * 8192];
static __device__ __half g_Wbth[4 * 2 * 8192];    // hpre weights
static __device__ __half g_LWth[4 * 3 * 8192];    // gates weights (K=192, 3 chunks)
// activation tiles, fp16, [group][chunk64][128x64]
static __device__ __half g_x1h[256 * 8 * 8192];   // pool A
static __device__ __half g_mAh[8 * 18 * 8192];    // m1 A (chunks 0..1 = h2 -> also hpre A)
static __device__ __half g_mBh[8 * 16 * 8192];    // m2 A
static __device__ __half g_gAh[8 * 3 * 8192];     // gates A: [din | h | h]

// ---------------- helpers ----------------
__device__ __forceinline__ uint32_t pack2hf(float v0, float v1) {
    __half2 h = __floats2half2_rn(v0, v1);
    return *(uint32_t*)&h;
}
__device__ __forceinline__ uint32_t smem_u32(const void* p) {
    uint32_t a;
    asm("{ .reg .u64 t; cvta.to.shared.u64 t, %1; cvt.u32.u64 %0, t; }" : "=r"(a) : "l"(p));
    return a;
}
__device__ __forceinline__ void cpa(uint32_t dsmem, const void* gsrc) {
    asm volatile("cp.async.cg.shared.global [%0], [%1], 16;" :: "r"(dsmem), "l"(gsrc) : "memory");
}
#define CPA_COMMIT() asm volatile("cp.async.commit_group;" ::: "memory")
#define CPA_WAIT1()  asm volatile("cp.async.wait_group 1;" ::: "memory")
#define CPA_WAIT0()  asm volatile("cp.async.wait_group 0;" ::: "memory")

// ---------------- consolidated prep (single launch) ----------------
__global__ __launch_bounds__(256) void prep_all(
    const float* __restrict__ h0, const float* __restrict__ c0,
    const float* __restrict__ last_pos, const float* __restrict__ last_pos_rel,
    const float* __restrict__ embW, const float* __restrict__ embb,
    const float* __restrict__ Wih, const float* __restrict__ Whh,
    const float* __restrict__ bih, const float* __restrict__ bhh,
    const float* __restrict__ sp_W, const float* __restrict__ sp_b,
    const float* __restrict__ pp1_W, const float* __restrict__ pp1_b,
    const float* __restrict__ pp1_g, const float* __restrict__ pp1_be,
    const float* __restrict__ pp2_W, const float* __restrict__ pp2_b,
    const float* __restrict__ pp2_g, const float* __restrict__ pp2_be,
    const float* __restrict__ m1_W, const float* __restrict__ m1_b,
    const float* __restrict__ m1_g, const float* __restrict__ m1_be,
    const float* __restrict__ m2_W, const float* __restrict__ m2_b,
    const float* __restrict__ m2_g, const float* __restrict__ m2_be) {
    int bid = blockIdx.x, tid = threadIdx.x;
    if (bid < 256) {
        for (int p = bid * 256 + tid; p < 1024 * 256; p += 256 * 256) {
            int co = p >> 8, kp = p & 255, k = kp * 2;
            int nb = co >> 7, r = co & 127, c = k >> 6;
            float s = BN_INV_F * pp2_g[co];
            float v0 = pp2_W[(size_t)co * B1D + k] * s, v1 = pp2_W[(size_t)co * B1D + k + 1] * s;
            ((uint32_t*)g_W2th)[(size_t)(nb * 8 + c) * 4096 + r * 32 + (kp & 31)] = pack2hf(v0, v1);
            if (kp == 0) g_bias2[co] = pp2_b[co] * s + pp2_be[co];
        }
    } else if (bid < 768) {
        for (int p = (bid - 256) * 256 + tid; p < 1024 * 576; p += 512 * 256) {
            int co = p / 576, kp = p % 576, k = kp * 2;
            int nb = co >> 7, r = co & 127, c = k >> 6;
            float s = BN_INV_F * m1_g[co];
            float v0 = m1_W[(size_t)co * KM1 + k] * s, v1 = m1_W[(size_t)co * KM1 + k + 1] * s;
            ((uint32_t*)g_M1th)[(size_t)(nb * 18 + c) * 4096 + r * 32 + (kp & 31)] = pack2hf(v0, v1);
            if (kp == 0) g_bm1[co] = m1_b[co] * s + m1_be[co];
        }
    } else if (bid < 832) {
        for (int p = (bid - 768) * 256 + tid; p < 128 * 512; p += 64 * 256) {
            int co = p >> 9, kp = p & 511, k = kp * 2;
            int r = co & 127, c = k >> 6;
            float s = BN_INV_F * m2_g[co];
            float v0 = m2_W[(size_t)co * M1D + k] * s, v1 = m2_W[(size_t)co * M1D + k + 1] * s;
            ((uint32_t*)g_M2th)[(size_t)c * 4096 + r * 32 + (kp & 31)] = pack2hf(v0, v1);
            if (kp == 0) g_bm2[co] = m2_b[co] * s + m2_be[co];
        }
    } else if (bid < 896) {
        for (int p = (bid - 832) * 256 + tid; p < 512 * 96; p += 64 * 256) {
            int r = p / 96, kp = p % 96, k = kp * 2;
            float v0 = (k < 64) ? Wih[r * 64 + k] : Whh[r * 128 + k - 64];
            float v1 = (k + 1 < 64) ? Wih[r * 64 + k + 1] : Whh[r * 128 + k + 1 - 64];
            int nb = r >> 7, rr = r & 127, kc = kp >> 5;
            ((uint32_t*)g_LWth)[(size_t)(nb * 3 + kc) * 4096 + rr * 32 + (kp & 31)] = pack2hf(v0, v1);
            if (kp == 0) g_Lb[r] = bih[r] + bhh[r];
        }
    } else if (bid < 898) {
        int k = (bid - 896) * 256 + tid;
        if (k < B1D) {
            float s1 = BN_INV_F * pp1_g[k];
            const float* row = pp1_W + (size_t)k * (ED + HD);
            float sa = 0.f, sb = 0.f, sc = 0.f;
            for (int e = 0; e < ED; e++) {
                float w = row[e];
                sa += w * sp_W[e * 2]; sb += w * sp_W[e * 2 + 1]; sc += w * sp_b[e];
            }
            g_A[k] = sa * s1; g_B[k] = sb * s1;
            g_bias1[k] = (pp1_b[k] + sc) * s1 + pp1_be[k];
            int nb = k >> 7, r = k & 127;
            for (int h = 0; h < HD; h += 2) {
                float w0 = row[ED + h] * s1, w1 = row[ED + h + 1] * s1;
                int c = h >> 6;
                ((uint32_t*)g_Wbth)[(size_t)(nb * 2 + c) * 4096 + r * 32 + ((h & 63) >> 1)] =
                    pack2hf(w0, w1);
            }
        }
    } else {
        for (int idx = (bid - 898) * 256 + tid; idx < NT * HD; idx += 126 * 256) {
            g_c[idx] = c0[idx];
            if (idx < NT * 2) g_lp[idx] = last_pos[idx];
            if ((idx & 1) == 0) {
                int ped = idx >> 7, h = idx & 127;
                int mb = ped >> 7, m = ped & 127;
                int ch = 1 + (h >> 6), kk = (h & 63) >> 1;
                ((uint32_t*)g_gAh)[(size_t)(mb * 3 + ch) * 4096 + m * 32 + kk] =
                    pack2hf(h0[idx], h0[idx + 1]);
            }
            if (idx < NT * ED && (idx & 1) == 0) {
                int n = idx >> 6, e = idx & 63;
                float lx = last_pos_rel[n * 2], ly = last_pos_rel[n * 2 + 1];
                float v0 = lx * embW[e * 2]       + ly * embW[e * 2 + 1]       + embb[e];
                float v1 = lx * embW[(e + 1) * 2] + ly * embW[(e + 1) * 2 + 1] + embb[e + 1];
                int mb = n >> 7, m = n & 127;
                ((uint32_t*)g_gAh)[(size_t)(mb * 3) * 4096 + m * 32 + (e >> 1)] = pack2hf(v0, v1);
            }
        }
    }
}

// ---------------- gates wmma: A = g_gAh (3 chunks), W = g_LWth ----------------
#define GA_SMEM 110592

__global__ __launch_bounds__(256) void gates_wmma() {
    extern __shared__ __align__(16) char smraw[];
    uint32_t base = smem_u32(smraw);
    float* c_s = (float*)smraw;
    int tid = threadIdx.x, w = tid >> 5;
    int wr = w >> 1, wc = w & 1;
    int nbX = blockIdx.x, mb = blockIdx.y;

    for (int c = 0; c < 3; c++) {
        const __half* At = g_gAh + (size_t)(mb * 3 + c) * 8192;
        const __half* Wt = g_LWth + (size_t)(nbX * 3 + c) * 8192;
        uint32_t sbA = base + c * 18432;
        uint32_t sbW = base + 55296 + c * 18432;
#pragma unroll
        for (int q = 0; q < 4; q++) {
            int i = tid + q * 256;
            int r = i >> 3, seg = i & 7;
            cpa(sbA + r * 144 + seg * 16, At + r * 64 + seg * 8);
            cpa(sbW + r * 144 + seg * 16, Wt + r * 64 + seg * 8);
        }
    }
    CPA_COMMIT();
    CPA_WAIT0();
    __syncthreads();

    wmma::fragment<wmma::accumulator, 16, 16, 16, float> acc[2][4];
#pragma unroll
    for (int mf = 0; mf < 2; mf++)
#pragma unroll
        for (int nf = 0; nf < 4; nf++) wmma::fill_fragment(acc[mf][nf], 0.f);

#pragma unroll
    for (int c = 0; c < 3; c++) {
        const __half* sA = (const __half*)(smraw + c * 18432);
        const __half* sW = (const __half*)(smraw + 55296 + c * 18432);
#pragma unroll
        for (int ks = 0; ks < 4; ks++) {
            wmma::fragment<wmma::matrix_a, 16, 16, 16, __half, wmma::row_major> af[2];
#pragma unroll
            for (int mf = 0; mf < 2; mf++)
                wmma::load_matrix_sync(af[mf], sA + (wr * 32 + mf * 16) * 72 + ks * 16, 72);
#pragma unroll
            for (int nf = 0; nf < 4; nf++) {
                wmma::fragment<wmma::matrix_b, 16, 16, 16, __half, wmma::col_major> bh;
                wmma::load_matrix_sync(bh, sW + (wc * 64 + nf * 16) * 72 + ks * 16, 72);
#pragma unroll
                for (int mf = 0; mf < 2; mf++)
                    wmma::mma_sync(acc[mf][nf], af[mf], bh, acc[mf][nf]);
            }
        }
    }
    __syncthreads();
#pragma unroll
    for (int mf = 0; mf < 2; mf++)
#pragma unroll
        for (int nf = 0; nf < 4; nf++)
            wmma::store_matrix_sync(c_s + (wr * 32 + mf * 16) * 136 + wc * 64 + nf * 16,
                                    acc[mf][nf], 136, wmma::mem_row_major);
    __syncthreads();
    for (int p = tid; p < 16384; p += 256) {
        int r = p >> 7, cc = p & 127;
        int col = nbX * 128 + cc;
        g_gates[(size_t)(mb * 128 + r) * 512 + col] = c_s[r * 136 + cc] + g_Lb[col];
    }
}

// ---------------- LSTM pointwise (warp-per-ped, no block barriers) ----------------
__global__ __launch_bounds__(256) void lstm_point(
    const float* __restrict__ posW, const float* __restrict__ posb,
    const float* __restrict__ embW, const float* __restrict__ embb,
    float* __restrict__ out_t) {
    int ped = blockIdx.x * 8 + (threadIdx.x >> 5);
    int lane = threadIdx.x & 31;
    float h2v[4];
    float r0 = 0.f, r1 = 0.f;
#pragma unroll
    for (int q = 0; q < 4; q++) {
        int t = lane + 32 * q;
        float gi = g_gates[(size_t)ped * 512 + t];
        float gf = g_gates[(size_t)ped * 512 + 128 + t];
        float gg = g_gates[(size_t)ped * 512 + 256 + t];
        float go = g_gates[(size_t)ped * 512 + 384 + t];
        float ig = 1.f / (1.f + expf(-gi));
        float fg = 1.f / (1.f + expf(-gf));
        float gv = tanhf(gg);
        float og = 1.f / (1.f + expf(-go));
        float c2 = fg * g_c[ped * HD + t] + ig * gv;
        float h2 = og * tanhf(c2);
        g_c[ped * HD + t] = c2;
        h2v[q] = h2;
        r0 = fmaf(h2, posW[t], r0);
        r1 = fmaf(h2, posW[HD + t], r1);
    }
#pragma unroll
    for (int off = 16; off >= 1; off >>= 1) {
        r0 += __shfl_xor_sync(0xffffffffu, r0, off);
        r1 += __shfl_xor_sync(0xffffffffu, r1, off);
    }
    float v0 = r0 + posb[0], v1 = r1 + posb[1];
    if (lane == 0) {
        out_t[ped * 2] = v0; out_t[ped * 2 + 1] = v1;
        g_lp[ped * 2] += v0; g_lp[ped * 2 + 1] += v1;
    }
    int mb = ped >> 7, m = ped & 127;
    // h2 pairs -> m1 A chunks 0..1 (also hpre A); pair (2u,2u+1) lives in lanes (2j,2j+1)
#pragma unroll
    for (int q = 0; q < 4; q++) {
        float nb = __shfl_down_sync(0xffffffffu, h2v[q], 1);
        if ((lane & 1) == 0) {
            int kp = (lane >> 1) + 16 * q;       // pair index 0..63
            int c = kp >> 5;
            ((uint32_t*)g_mAh)[(size_t)(mb * 18 + c) * 4096 + m * 32 + (kp & 31)] =
                pack2hf(h2v[q], nb);
        }
    }
    // din pairs -> gates A chunk 0 (lane handles e = 2*lane, 2*lane+1)
    {
        int e0 = 2 * lane, e1 = e0 + 1;
        float d0 = fmaf(v0, embW[e0 * 2], fmaf(v1, embW[e0 * 2 + 1], embb[e0]));
        float d1 = fmaf(v0, embW[e1 * 2], fmaf(v1, embW[e1 * 2 + 1], embb[e1]));
        ((uint32_t*)g_gAh)[(size_t)(mb * 3) * 4096 + m * 32 + lane] = pack2hf(d0, d1);
    }
}

// ---------------- hpre wmma ----------------
#define HP_SMEM 73728

__global__ __launch_bounds__(256, 2) void hpre_wmma() {
    extern __shared__ __align__(16) char smraw[];
    uint32_t base = smem_u32(smraw);
    float* c_s = (float*)smraw;
    int tid = threadIdx.x, w = tid >> 5;
    int wr = w >> 1, wc = w & 1;
    int nbX = blockIdx.x, mb = blockIdx.y;

    for (int c = 0; c < 2; c++) {
        const __half* At = g_mAh + (size_t)(mb * 18 + c) * 8192;
        const __half* Wt = g_Wbth + (size_t)(nbX * 2 + c) * 8192;
        uint32_t sbA = base + c * 18432;
        uint32_t sbW = base + 36864 + c * 18432;
#pragma unroll
        for (int q = 0; q < 4; q++) {
            int i = tid + q * 256;
            int r = i >> 3, seg = i & 7;
            cpa(sbA + r * 144 + seg * 16, At + r * 64 + seg * 8);
            cpa(sbW + r * 144 + seg * 16, Wt + r * 64 + seg * 8);
        }
    }
    CPA_COMMIT();
    CPA_WAIT0();
    __syncthreads();

    wmma::fragment<wmma::accumulator, 16, 16, 16, float> acc[2][4];
#pragma unroll
    for (int mf = 0; mf < 2; mf++)
#pragma unroll
        for (int nf = 0; nf < 4; nf++) wmma::fill_fragment(acc[mf][nf], 0.f);

#pragma unroll
    for (int c = 0; c < 2; c++) {
        const __half* sA = (const __half*)(smraw + c * 18432);
        const __half* sW = (const __half*)(smraw + 36864 + c * 18432);
#pragma unroll
        for (int ks = 0; ks < 4; ks++) {
            wmma::fragment<wmma::matrix_a, 16, 16, 16, __half, wmma::row_major> af[2];
#pragma unroll
            for (int mf = 0; mf < 2; mf++)
                wmma::load_matrix_sync(af[mf], sA + (wr * 32 + mf * 16) * 72 + ks * 16, 72);
#pragma unroll
            for (int nf = 0; nf < 4; nf++) {
                wmma::fragment<wmma::matrix_b, 16, 16, 16, __half, wmma::col_major> bh;
                wmma::load_matrix_sync(bh, sW + (wc * 64 + nf * 16) * 72 + ks * 16, 72);
#pragma unroll
                for (int mf = 0; mf < 2; mf++)
                    wmma::mma_sync(acc[mf][nf], af[mf], bh, acc[mf][nf]);
            }
        }
    }
    __syncthreads();
#pragma unroll
    for (int mf = 0; mf < 2; mf++)
#pragma unroll
        for (int nf = 0; nf < 4; nf++)
            wmma::store_matrix_sync(c_s + (wr * 32 + mf * 16) * 136 + wc * 64 + nf * 16,
                                    acc[mf][nf], 136, wmma::mem_row_major);
    __syncthreads();
    for (int p = tid; p < 16384; p += 256) {
        int r = p >> 7, cc = p & 127;
        int col = nbX * 128 + cc;
        g_hpre[(size_t)(mb * 128 + r) * B1D + col] = c_s[r * 136 + cc] + g_bias1[col];
    }
}

// ---------------- build x1 fp16 tiles ----------------
__global__ __launch_bounds__(256) void build_x1() {
    int c = blockIdx.x, ib = blockIdx.y, s = blockIdx.z;
    int tid = threadIdx.x;
    __shared__ float rxs[128], rys[128];
    if (tid < 128) {
        int i = ib * 4 + (tid >> 5), j = tid & 31;
        float dx = g_lp[(s * 32 + j) * 2]     - g_lp[(s * 32 + i) * 2];
        float dy = g_lp[(s * 32 + j) * 2 + 1] - g_lp[(s * 32 + i) * 2 + 1];
        float nrm = fmaxf(sqrtf(dx * dx + dy * dy), 1e-12f);
        rxs[tid] = dx / nrm; rys[tid] = dy / nrm;
    }
    __syncthreads();
    int grp = s * 8 + ib;
    uint32_t* oh = (uint32_t*)g_x1h + (size_t)(grp * 8 + c) * 4096;
    int kp = tid & 31, k = c * 64 + kp * 2;
    float2 ab0 = *(const float2*)(g_A + k);
    float2 bb0 = *(const float2*)(g_B + k);
#pragma unroll
    for (int q = 0; q < 16; q++) {
        int m = (tid >> 5) + q * 8;
        int pj = s * 32 + (m & 31);
        float rx = rxs[m], ry = rys[m];
        float2 hp = *(const float2*)(g_hpre + (size_t)pj * B1D + k);
        float v0 = fmaxf(hp.x + rx * ab0.x + ry * bb0.x, 0.f);
        float v1 = fmaxf(hp.y + rx * ab0.y + ry * bb0.y, 0.f);
        oh[m * 32 + kp] = pack2hf(v0, v1);
    }
}

// ---------------- pool wmma: k=64 chunks (KC=8), 2-stage, 2 CTAs/SM ----------------
#define POOL_SS 36864
#define POOL_SMEM 73728

__global__ __launch_bounds__(256, 2) void pool_gemm() {
    extern __shared__ __align__(16) char smraw[];
    uint32_t base = smem_u32(smraw);
    float* c_s = (float*)smraw;
    int tid = threadIdx.x, w = tid >> 5;
    int wr = w >> 1, wc = w & 1;
    int nbX = blockIdx.x, grpY = blockIdx.y;

    auto stage = [&](int buf, int c) {
        uint32_t sb = base + buf * POOL_SS;
        const __half* At = g_x1h + (size_t)(grpY * 8 + c) * 8192;
        const __half* Wt = g_W2th + (size_t)(nbX * 8 + c) * 8192;
#pragma unroll
        for (int q = 0; q < 4; q++) {
            int i = tid + q * 256;
            int r = i >> 3, seg = i & 7;
            cpa(sb + r * 144 + seg * 16, At + r * 64 + seg * 8);
            cpa(sb + 18432 + r * 144 + seg * 16, Wt + r * 64 + seg * 8);
        }
        CPA_COMMIT();
    };

    wmma::fragment<wmma::accumulator, 16, 16, 16, float> acc[2][4];
#pragma unroll
    for (int mf = 0; mf < 2; mf++)
#pragma unroll
        for (int nf = 0; nf < 4; nf++) wmma::fill_fragment(acc[mf][nf], 0.f);

    stage(0, 0);
    for (int c = 0; c < 8; c++) {
        if (c + 1 < 8) { stage((c + 1) & 1, c + 1); CPA_WAIT1(); } else { CPA_WAIT0(); }
        __syncthreads();
        const __half* sbuf = (const __half*)(smraw + (c & 1) * POOL_SS);
        const __half* whp = sbuf + 9216;
#pragma unroll
        for (int ks = 0; ks < 4; ks++) {
            wmma::fragment<wmma::matrix_a, 16, 16, 16, __half, wmma::row_major> af[2];
#pragma unroll
            for (int mf = 0; mf < 2; mf++)
                wmma::load_matrix_sync(af[mf], sbuf + (wr * 32 + mf * 16) * 72 + ks * 16, 72);
#pragma unroll
            for (int nf = 0; nf < 4; nf++) {
                wmma::fragment<wmma::matrix_b, 16, 16, 16, __half, wmma::col_major> bh;
                wmma::load_matrix_sync(bh, whp + (wc * 64 + nf * 16) * 72 + ks * 16, 72);
#pragma unroll
                for (int mf = 0; mf < 2; mf++)
                    wmma::mma_sync(acc[mf][nf], af[mf], bh, acc[mf][nf]);
            }
        }
        __syncthreads();
    }

    __syncthreads();
#pragma unroll
    for (int mf = 0; mf < 2; mf++)
#pragma unroll
        for (int nf = 0; nf < 4; nf++)
            wmma::store_matrix_sync(c_s + (wr * 32 + mf * 16) * 136 + wc * 64 + nf * 16,
                                    acc[mf][nf], 136, wmma::mem_row_major);
    __syncthreads();

    int s = grpY >> 3, ib = grpY & 7;
    {
        int il = tid >> 6, kp0 = tid & 63;
        int cc0 = kp0 * 2;
        float m0 = c_s[(il * 32) * 136 + cc0];
        float m1v = c_s[(il * 32) * 136 + cc0 + 1];
#pragma unroll 8
        for (int r = 1; r < 32; r++) {
            m0  = fmaxf(m0,  c_s[(il * 32 + r) * 136 + cc0]);
            m1v = fmaxf(m1v, c_s[(il * 32 + r) * 136 + cc0 + 1]);
        }
        int col = nbX * 128 + cc0;
        float v0 = fmaxf(m0 + g_bias2[col], 0.f);
        float v1 = fmaxf(m1v + g_bias2[col + 1], 0.f);
        int ped = s * 32 + ib * 4 + il;
        int mb = ped >> 7, m = ped & 127;
        int cch = 2 + nbX * 2 + (kp0 >> 5);
        ((uint32_t*)g_mAh)[(size_t)(mb * 18 + cch) * 4096 + m * 32 + (kp0 & 31)] =
            pack2hf(v0, v1);
    }
}

// ---------------- m1 wmma (grid 8x16, ROWS=64, KC=36) ----------------
__global__ __launch_bounds__(256, 2) void m1_wmma() {
    constexpr int KC = 36;
    constexpr int SA = 64 * 80;
    constexpr int SS = SA + 10240;
    extern __shared__ __align__(16) char smraw[];
    uint32_t base = smem_u32(smraw);
    float* c_s = (float*)smraw;

    int tid = threadIdx.x, w = tid >> 5;
    int wr = w / 4, wc = w % 4;
    int nbX = blockIdx.x, grpY = blockIdx.y;

    auto stage = [&](int buf, int c) {
        int ch = c >> 1, sub = c & 1;
        int tile0 = (grpY >> 1) * 18 + ch, roff = (grpY & 1) * 64;
        int wtile = nbX * 18 + ch;
        uint32_t sb = base + buf * SS;
        for (int i = tid; i < 256; i += 256) {
            int r = i >> 2, seg = i & 3;
            size_t so = (size_t)tile0 * 8192 + (roff + r) * 64 + sub * 32 + seg * 8;
            cpa(sb + r * 80 + seg * 16, g_mAh + so);
        }
        for (int i = tid; i < 512; i += 256) {
            int r = i >> 2, seg = i & 3;
            size_t so = (size_t)wtile * 8192 + r * 64 + sub * 32 + seg * 8;
            cpa(sb + SA + r * 80 + seg * 16, g_M1th + so);
        }
        CPA_COMMIT();
    };

    wmma::fragment<wmma::accumulator, 16, 16, 16, float> acc[2][2];
#pragma unroll
    for (int mf = 0; mf < 2; mf++)
#pragma unroll
        for (int nf = 0; nf < 2; nf++) wmma::fill_fragment(acc[mf][nf], 0.f);

    stage(0, 0);
    for (int c = 0; c < KC; c++) {
        if (c + 1 < KC) { stage((c + 1) & 1, c + 1); CPA_WAIT1(); } else { CPA_WAIT0(); }
        __syncthreads();
        const __half* sbuf = (const __half*)(smraw + (c & 1) * SS);
        const __half* whp = sbuf + SA / 2;
#pragma unroll
        for (int ks = 0; ks < 2; ks++) {
            wmma::fragment<wmma::matrix_a, 16, 16, 16, __half, wmma::row_major> af[2];
#pragma unroll
            for (int mf = 0; mf < 2; mf++)
                wmma::load_matrix_sync(af[mf], sbuf + (wr * 32 + mf * 16) * 40 + ks * 16, 40);
#pragma unroll
            for (int nf = 0; nf < 2; nf++) {
                wmma::fragment<wmma::matrix_b, 16, 16, 16, __half, wmma::col_major> bh;
                wmma::load_matrix_sync(bh, whp + (wc * 32 + nf * 16) * 40 + ks * 16, 40);
#pragma unroll
                for (int mf = 0; mf < 2; mf++)
                    wmma::mma_sync(acc[mf][nf], af[mf], bh, acc[mf][nf]);
            }
        }
        __syncthreads();
    }

    __syncthreads();
#pragma unroll
    for (int mf = 0; mf < 2; mf++)
#pragma unroll
        for (int nf = 0; nf < 2; nf++)
            wmma::store_matrix_sync(c_s + (wr * 32 + mf * 16) * 136 + wc * 32 + nf * 16,
                                    acc[mf][nf], 136, wmma::mem_row_major);
    __syncthreads();

    for (int p = tid; p < 4096; p += 256) {
        int r = p >> 6, kp = p & 63;
        int cc0 = kp * 2, col = nbX * 128 + cc0;
        float v0 = fmaxf(c_s[r * 136 + cc0]     + g_bm1[col], 0.f);
        float v1 = fmaxf(c_s[r * 136 + cc0 + 1] + g_bm1[col + 1], 0.f);
        int ped = grpY * 64 + r;
        int mb = ped >> 7, m = ped & 127;
        int cch = nbX * 2 + (kp >> 5);
        ((uint32_t*)g_mBh)[(size_t)(mb * 16 + cch) * 4096 + m * 32 + (kp & 31)] =
            pack2hf(v0, v1);
    }
}

// ---------------- m2 wmma full-K (grid 8 mb, KC=16) + h pack into gates A ----------------
__global__ __launch_bounds__(256, 2) void m2_wmma() {
    extern __shared__ __align__(16) char smraw[];
    uint32_t base = smem_u32(smraw);
    float* c_s = (float*)smraw;
    int tid = threadIdx.x, w = tid >> 5;
    int wr = w >> 1, wc = w & 1;
    int mb = blockIdx.x;

    auto stage = [&](int buf, int c) {
        uint32_t sb = base + buf * POOL_SS;
        const __half* At = g_mBh + (size_t)(mb * 16 + c) * 8192;
        const __half* Wt = g_M2th + (size_t)c * 8192;
#pragma unroll
        for (int q = 0; q < 4; q++) {
            int i = tid + q * 256;
            int r = i >> 3, seg = i & 7;
            cpa(sb + r * 144 + seg * 16, At + r * 64 + seg * 8);
            cpa(sb + 18432 + r * 144 + seg * 16, Wt + r * 64 + seg * 8);
        }
        CPA_COMMIT();
    };

    wmma::fragment<wmma::accumulator, 16, 16, 16, float> acc[2][4];
#pragma unroll
    for (int mf = 0; mf < 2; mf++)
#pragma unroll
        for (int nf = 0; nf < 4; nf++) wmma::fill_fragment(acc[mf][nf], 0.f);

    stage(0, 0);
    for (int c = 0; c < 16; c++) {
        if (c + 1 < 16) { stage((c + 1) & 1, c + 1); CPA_WAIT1(); } else { CPA_WAIT0(); }
        __syncthreads();
        const __half* sbuf = (const __half*)(smraw + (c & 1) * POOL_SS);
        const __half* whp = sbuf + 9216;
#pragma unroll
        for (int ks = 0; ks < 4; ks++) {
            wmma::fragment<wmma::matrix_a, 16, 16, 16, __half, wmma::row_major> af[2];
#pragma unroll
            for (int mf = 0; mf < 2; mf++)
                wmma::load_matrix_sync(af[mf], sbuf + (wr * 32 + mf * 16) * 72 + ks * 16, 72);
#pragma unroll
            for (int nf = 0; nf < 4; nf++) {
                wmma::fragment<wmma::matrix_b, 16, 16, 16, __half, wmma::col_major> bh;
                wmma::load_matrix_sync(bh, whp + (wc * 64 + nf * 16) * 72 + ks * 16, 72);
#pragma unroll
                for (int mf = 0; mf < 2; mf++)
                    wmma::mma_sync(acc[mf][nf], af[mf], bh, acc[mf][nf]);
            }
        }
        __syncthreads();
    }

    __syncthreads();
#pragma unroll
    for (int mf = 0; mf < 2; mf++)
#pragma unroll
        for (int nf = 0; nf < 4; nf++)
            wmma::store_matrix_sync(c_s + (wr * 32 + mf * 16) * 136 + wc * 64 + nf * 16,
                                    acc[mf][nf], 136, wmma::mem_row_major);
    __syncthreads();
    // h(t+1) = relu(x + bm2) -> gates A chunks 1..2 (fp16)
    for (int p = tid; p < 8192; p += 256) {
        int r = p >> 6, kp = p & 63;
        int cc0 = kp * 2;
        float v0 = fmaxf(c_s[r * 136 + cc0]     + g_bm2[cc0], 0.f);
        float v1 = fmaxf(c_s[r * 136 + cc0 + 1] + g_bm2[cc0 + 1], 0.f);
        int ch = 1 + (cc0 >> 6);
        ((uint32_t*)g_gAh)[(size_t)(mb * 3 + ch) * 4096 + r * 32 + (kp & 31)] =
            pack2hf(v0, v1);
    }
}

// ---------------- host launch ----------------
extern "C" void kernel_launch(void* const* d_in, const int* in_sizes, int n_in,
                              void* d_out, int out_size) {
    const float* last_pos     = (const float*)d_in[0];
    const float* last_pos_rel = (const float*)d_in[1];
    const float* h0  = (const float*)d_in[2];
    const float* c0  = (const float*)d_in[3];
    const float* emb_W = (const float*)d_in[5];
    const float* emb_b = (const float*)d_in[6];
    const float* Wih = (const float*)d_in[7];
    const float* Whh = (const float*)d_in[8];
    const float* bih = (const float*)d_in[9];
    const float* bhh = (const float*)d_in[10];
    const float* pos_W = (const float*)d_in[11];
    const float* pos_b = (const float*)d_in[12];
    const float* sp_W = (const float*)d_in[13];
    const float* sp_b = (const float*)d_in[14];
    const float* pp1_W = (const float*)d_in[15];
    const float* pp1_b = (const float*)d_in[16];
    const float* pp1_g = (const float*)d_in[17];
    const float* pp1_be = (const float*)d_in[18];
    const float* pp2_W = (const float*)d_in[19];
    const float* pp2_b = (const float*)d_in[20];
    const float* pp2_g = (const float*)d_in[21];
    const float* pp2_be = (const float*)d_in[22];
    const float* m1_W = (const float*)d_in[23];
    const float* m1_b = (const float*)d_in[24];
    const float* m1_g = (const float*)d_in[25];
    const float* m1_be = (const float*)d_in[26];
    const float* m2_W = (const float*)d_in[27];
    const float* m2_b = (const float*)d_in[28];
    const float* m2_g = (const float*)d_in[29];
    const float* m2_be = (const float*)d_in[30];
    float* out = (float*)d_out;

    cudaFuncSetAttribute(gates_wmma, cudaFuncAttributeMaxDynamicSharedMemorySize, GA_SMEM);
    cudaFuncSetAttribute(hpre_wmma, cudaFuncAttributeMaxDynamicSharedMemorySize, HP_SMEM);
    cudaFuncSetAttribute(pool_gemm, cudaFuncAttributeMaxDynamicSharedMemorySize, POOL_SMEM);
    cudaFuncSetAttribute(m1_wmma, cudaFuncAttributeMaxDynamicSharedMemorySize, 36864);
    cudaFuncSetAttribute(m2_wmma, cudaFuncAttributeMaxDynamicSharedMemorySize, POOL_SMEM);

    prep_all<<<1024, 256>>>(h0, c0, last_pos, last_pos_rel, emb_W, emb_b,
                            Wih, Whh, bih, bhh, sp_W, sp_b,
                            pp1_W, pp1_b, pp1_g, pp1_be,
                            pp2_W, pp2_b, pp2_g, pp2_be,
                            m1_W, m1_b, m1_g, m1_be,
                            m2_W, m2_b, m2_g, m2_be);

    for (int t = 0; t < TS; t++) {
        gates_wmma<<<dim3(4, 8), 256, GA_SMEM>>>();
        lstm_point<<<128, 256>>>(pos_W, pos_b, emb_W, emb_b, out + (size_t)t * NT * 2);
        hpre_wmma<<<dim3(4, 8), 256, HP_SMEM>>>();
        build_x1<<<dim3(8, 8, SC), 256>>>();
        pool_gemm<<<dim3(8, 256), 256, POOL_SMEM>>>();
        m1_wmma<<<dim3(8, 16), 256, 36864>>>();
        m2_wmma<<<8, 256, POOL_SMEM>>>();
    }
    (void)in_sizes; (void)n_in; (void)out_size;
}